// round 10
// baseline (speedup 1.0000x reference)
#include <cuda_runtime.h>
#include <mma.h>
#include <math.h>
#include <stdint.h>

using namespace nvcuda;

#define TOTPTS 16384
#define MROWS  131072   // TOT*NV
#define KDIM   2048
#define NDIM   512
#define MT_ROWS 114688  // rows on tensor path (7/8); rest on FFMA path

// Static device scratch (no runtime allocation allowed).
__device__ float g_W0T[(size_t)NDIM * KDIM];       // W0^T [n][k], tf32-RN, 4MB
__device__ float g_part[(size_t)4 * MROWS * 32];   // per-N-chunk partial B32, 64MB

__device__ __forceinline__ float eluf(float x) { return x > 0.f ? x : expm1f(x); }
__device__ __forceinline__ float sigm(float x) { return 1.f / (1.f + expf(-x)); }
__device__ __forceinline__ float wrsum(float v) {
#pragma unroll
    for (int o = 16; o > 0; o >>= 1) v += __shfl_xor_sync(0xffffffffu, v, o);
    return v;
}
__device__ __forceinline__ float rnd_tf32(float x) {
    float r;
    asm("cvt.rna.tf32.f32 %0, %1;" : "=f"(r) : "f"(x));
    return r;
}
__device__ __forceinline__ uint32_t smem_u32(const void* p) {
    uint32_t a;
    asm("{ .reg .u64 t; cvta.to.shared.u64 t, %1; cvt.u32.u64 %0, t; }" : "=r"(a) : "l"(p));
    return a;
}
__device__ __forceinline__ void bulkcp(uint32_t dst, const void* src, uint32_t bytes,
                                       uint32_t bar) {
    asm volatile("cp.async.bulk.shared::cta.global.mbarrier::complete_tx::bytes "
                 "[%0], [%1], %2, [%3];"
                 :: "r"(dst), "l"(src), "r"(bytes), "r"(bar) : "memory");
}
__device__ __forceinline__ void cp16(void* smem_dst, const void* gmem_src) {
    unsigned int s = (unsigned int)__cvta_generic_to_shared(smem_dst);
    asm volatile("cp.async.cg.shared.global [%0], [%1], 16;\n" :: "r"(s), "l"(gmem_src));
}
__device__ __forceinline__ void cp_commit() { asm volatile("cp.async.commit_group;\n"); }
template <int N>
__device__ __forceinline__ void cp_wait() { asm volatile("cp.async.wait_group %0;\n" :: "n"(N)); }
__device__ __forceinline__ void ldsm4(uint32_t& r0, uint32_t& r1, uint32_t& r2, uint32_t& r3,
                                      uint32_t addr) {
    asm volatile("ldmatrix.sync.aligned.m8n8.x4.shared.b16 {%0,%1,%2,%3}, [%4];"
                 : "=r"(r0), "=r"(r1), "=r"(r2), "=r"(r3) : "r"(addr));
}
__device__ __forceinline__ void mma8(float* d, const uint32_t* a, const uint32_t* b) {
    asm volatile("mma.sync.aligned.m16n8k8.row.col.f32.tf32.tf32.f32 "
                 "{%0,%1,%2,%3}, {%4,%5,%6,%7}, {%8,%9}, {%0,%1,%2,%3};"
                 : "+f"(d[0]), "+f"(d[1]), "+f"(d[2]), "+f"(d[3])
                 : "r"(a[0]), "r"(a[1]), "r"(a[2]), "r"(a[3]), "r"(b[0]), "r"(b[1]));
}
#define MBAR_INIT(a, c) asm volatile("mbarrier.init.shared.b64 [%0], %1;" :: "r"(a), "r"(c) : "memory")
#define MBAR_EXPECT(a, tx) asm volatile("mbarrier.arrive.expect_tx.shared.b64 _, [%0], %1;" :: "r"(a), "r"(tx) : "memory")
#define MBAR_WAIT(a, ph) do {                                                              \
    uint32_t _m = (a), _p = (ph), _d;                                                      \
    asm volatile("{\n\t.reg .pred p;\n\t"                                                  \
                 "mbarrier.try_wait.parity.acquire.cta.shared::cta.b64 p, [%1], %2;\n\t"   \
                 "selp.b32 %0, 1, 0, p;\n\t}" : "=r"(_d) : "r"(_m), "r"(_p) : "memory");   \
    if (!_d) {                                                                             \
        asm volatile("{\n\t.reg .pred P1;\n\t"                                             \
            "WL%=:\n\t"                                                                    \
            "mbarrier.try_wait.parity.acquire.cta.shared::cta.b64 P1, [%0], %1, 0x989680;\n\t" \
            "@P1 bra.uni WD%=;\n\t"                                                        \
            "bra.uni WL%=;\n\t"                                                            \
            "WD%=:\n\t}" :: "r"(_m), "r"(_p) : "memory");                                  \
    }                                                                                      \
} while (0)
#define FENCE_PROXY() asm volatile("fence.proxy.async.shared::cta;" ::: "memory")

// ---------------------------------------------------------------------------
// PREP: g_W0T[n][k] = rn_tf32(W0[k][n])
// ---------------------------------------------------------------------------
__global__ void prep_w0t(const float* __restrict__ W0) {
    __shared__ float tile[32][33];
    int n0 = blockIdx.x * 32, k0 = blockIdx.y * 32;
    int tx = threadIdx.x, ty = threadIdx.y;
#pragma unroll
    for (int j = 0; j < 32; j += 8)
        tile[ty + j][tx] = W0[(size_t)(k0 + ty + j) * NDIM + n0 + tx];
    __syncthreads();
#pragma unroll
    for (int j = 0; j < 32; j += 8)
        g_W0T[(size_t)(n0 + ty + j) * KDIM + k0 + tx] = rnd_tf32(tile[tx][ty + j]);
}

// ---------------------------------------------------------------------------
// GEMM1 hybrid: 4096 blocks, interleaved 7:1.
//   rem<7 : tensor path (mma.tf32 + ldmatrix + bulkcp 2-stage) rows [0,114688)
//   rem==7: FFMA path (classic SGEMM 128x128, 8x8 microtile) rows [114688,131072)
// Both share the wmma H@W1 epilogue -> g_part[p].
// ---------------------------------------------------------------------------
#define STAGEB   36864
#define SMEM_G1  88064
#define HS_F     256
#define W1S_F    17152
// FFMA-path stage buffers (float indices): A [128][20] x2, B [16][132] x2
#define FA0      256
#define FASTR    2560
#define FB0      5376
#define FBSTR    2112

__global__ void __launch_bounds__(256, 2) gemm1_kernel(
    const float* __restrict__ X, const float* __restrict__ b0,
    const float* __restrict__ W1, const float* __restrict__ W0raw)
{
    extern __shared__ float sm[];
    const uint32_t smem = smem_u32(sm);
    const int tid = threadIdx.x, wid = tid >> 5, lane = tid & 31;

    const int bid = blockIdx.x;
    const int grp = bid >> 3, rem = bid & 7;
    const bool is_ffma = (rem == 7);
    int p, m0;
    if (!is_ffma) { int lt = grp * 7 + rem; p = lt & 3; m0 = (lt >> 2) * 128; }
    else          { p = grp & 3;            m0 = MT_ROWS + (grp >> 2) * 128; }
    const int n0 = p * 128;

    if (tid < 128) sm[32 + tid] = b0[n0 + tid];
    if (tid == 0) {
        MBAR_INIT(smem + 16, 1);
        MBAR_INIT(smem + 24, 1);
        FENCE_PROXY();
    }
    __syncthreads();

    float* Hs  = sm + HS_F;     // 128 x 132
    float* W1s = sm + W1S_F;    // 128 x 36

    if (!is_ffma) {
        // ================= tensor path (unchanged from round 8/9) ==========
        const int wm = (wid >> 2) * 64, wn = (wid & 3) * 32;
        const bool isA = tid < 128;
        const int row = tid & 127;
        const float* srcbase = isA ? (X + (size_t)(m0 + row) * KDIM)
                                   : (g_W0T + (size_t)(n0 + row) * KDIM);
        const uint32_t dsto = (isA ? 0u : 18432u) + (uint32_t)row * 144u;

        float acc[4][4][4];
#pragma unroll
        for (int g = 0; g < 4; g++)
#pragma unroll
            for (int j = 0; j < 4; j++)
#pragma unroll
                for (int e = 0; e < 4; e++) acc[g][j][e] = 0.f;

        const int rA = lane & 15, hA = (lane >> 4) & 1;
        const int rB = (lane & 7) + ((lane >> 4) & 1) * 8, hB = (lane >> 3) & 1;
        const uint32_t aoff = (uint32_t)(wm + rA) * 144u + (uint32_t)hA * 16u;
        const uint32_t boff = 18432u + (uint32_t)(wn + rB) * 144u + (uint32_t)hB * 16u;

#pragma unroll
        for (int t = 0; t < 2; t++) {
            uint32_t bar = smem + 16 + 8 * t;
            if (tid == 0) MBAR_EXPECT(bar, 32768);
            __syncwarp();
            bulkcp(smem + 1024 + t * STAGEB + dsto, srcbase + t * 32, 128, bar);
        }

        for (int t = 0; t < 64; t++) {
            const int s = t & 1;
            MBAR_WAIT(smem + 16 + 8 * s, (t >> 1) & 1);

            const uint32_t base = smem + 1024 + s * STAGEB;
#pragma unroll
            for (int ks = 0; ks < 4; ks++) {
                uint32_t a[4][4], b[2][4];
#pragma unroll
                for (int g = 0; g < 4; g++)
                    ldsm4(a[g][0], a[g][1], a[g][2], a[g][3],
                          base + aoff + (uint32_t)g * 2304u + (uint32_t)ks * 32u);
#pragma unroll
                for (int jj = 0; jj < 2; jj++)
                    ldsm4(b[jj][0], b[jj][1], b[jj][2], b[jj][3],
                          base + boff + (uint32_t)jj * 2304u + (uint32_t)ks * 32u);
#pragma unroll
                for (int g = 0; g < 4; g++)
#pragma unroll
                    for (int e = 0; e < 4; e++)
                        a[g][e] = __float_as_uint(rnd_tf32(__uint_as_float(a[g][e])));
#pragma unroll
                for (int g = 0; g < 4; g++) {
                    mma8(acc[g][0], a[g], &b[0][0]);
                    mma8(acc[g][1], a[g], &b[0][2]);
                    mma8(acc[g][2], a[g], &b[1][0]);
                    mma8(acc[g][3], a[g], &b[1][2]);
                }
            }
            __syncthreads();
            if (t + 2 < 64) {
                uint32_t bar = smem + 16 + 8 * s;
                if (tid == 0) MBAR_EXPECT(bar, 32768);
                bulkcp(smem + 1024 + s * STAGEB + dsto, srcbase + (t + 2) * 32, 128, bar);
            }
        }

        // Hs = tf32(elu(acc + b0)) from mma registers
        {
            const int tr = lane >> 2, tc = 2 * (lane & 3);
#pragma unroll
            for (int g = 0; g < 4; g++)
#pragma unroll
                for (int j = 0; j < 4; j++) {
                    int R0 = wm + g * 16 + tr, C = wn + j * 8 + tc;
                    float b0c0 = sm[32 + C], b0c1 = sm[32 + C + 1];
                    float2 v0, v1;
                    v0.x = rnd_tf32(eluf(acc[g][j][0] + b0c0));
                    v0.y = rnd_tf32(eluf(acc[g][j][1] + b0c1));
                    v1.x = rnd_tf32(eluf(acc[g][j][2] + b0c0));
                    v1.y = rnd_tf32(eluf(acc[g][j][3] + b0c1));
                    *(float2*)&Hs[R0 * 132 + C] = v0;
                    *(float2*)&Hs[(R0 + 8) * 132 + C] = v1;
                }
        }
    } else {
        // ================= FFMA path (raw fp32 SGEMM) ======================
        const int tx = tid & 15, ty = tid >> 4;   // 16x16 threads, 8x8 microtile
        float c[8][8];
#pragma unroll
        for (int i = 0; i < 8; i++)
#pragma unroll
            for (int j = 0; j < 8; j++) c[i][j] = 0.f;

        // prologue: stage 0 (k0 = 0)
        {
            float* A = sm + FA0;
            float* B = sm + FB0;
#pragma unroll
            for (int i = tid; i < 512; i += 256) {          // A: 128 x 16
                int r = i >> 2, seg = i & 3;
                cp16(&A[r * 20 + seg * 4], X + (size_t)(m0 + r) * KDIM + seg * 4);
            }
#pragma unroll
            for (int i = tid; i < 512; i += 256) {          // B: 16 x 128
                int r = i >> 5, seg = i & 31;
                cp16(&B[r * 132 + seg * 4], W0raw + (size_t)r * NDIM + n0 + seg * 4);
            }
            cp_commit();
        }

        for (int t = 0; t < 128; t++) {
            const int s = t & 1;
            if (t + 1 < 128) {
                const int sn = (t + 1) & 1, k0 = (t + 1) * 16;
                float* A = sm + FA0 + sn * FASTR;
                float* B = sm + FB0 + sn * FBSTR;
#pragma unroll
                for (int i = tid; i < 512; i += 256) {
                    int r = i >> 2, seg = i & 3;
                    cp16(&A[r * 20 + seg * 4], X + (size_t)(m0 + r) * KDIM + k0 + seg * 4);
                }
#pragma unroll
                for (int i = tid; i < 512; i += 256) {
                    int r = i >> 5, seg = i & 31;
                    cp16(&B[r * 132 + seg * 4], W0raw + (size_t)(k0 + r) * NDIM + n0 + seg * 4);
                }
                cp_commit();
                cp_wait<1>();
            } else {
                cp_wait<0>();
            }
            __syncthreads();

            const float* A = sm + FA0 + s * FASTR;
            const float* B = sm + FB0 + s * FBSTR;
#pragma unroll
            for (int kk = 0; kk < 16; kk++) {
                float av[8];
#pragma unroll
                for (int i = 0; i < 8; i++) av[i] = A[(ty * 8 + i) * 20 + kk];
                float4 bx = *(const float4*)&B[kk * 132 + tx * 8];
                float4 by = *(const float4*)&B[kk * 132 + tx * 8 + 4];
#pragma unroll
                for (int i = 0; i < 8; i++) {
                    c[i][0] += av[i] * bx.x; c[i][1] += av[i] * bx.y;
                    c[i][2] += av[i] * bx.z; c[i][3] += av[i] * bx.w;
                    c[i][4] += av[i] * by.x; c[i][5] += av[i] * by.y;
                    c[i][6] += av[i] * by.z; c[i][7] += av[i] * by.w;
                }
            }
            __syncthreads();
        }

        // Hs = tf32(elu(c + b0))
#pragma unroll
        for (int i = 0; i < 8; i++)
#pragma unroll
            for (int j = 0; j < 8; j++) {
                int C = tx * 8 + j;
                Hs[(ty * 8 + i) * 132 + C] = rnd_tf32(eluf(c[i][j] + sm[32 + C]));
            }
    }

    // ===================== common epilogue: partial B32 = Hs @ W1chunk =====
    for (int i = tid; i < 128 * 32; i += 256) {
        int r = i >> 5, cc = i & 31;
        W1s[r * 36 + cc] = rnd_tf32(W1[(size_t)(n0 + r) * 32 + cc]);
    }
    __syncthreads();

    {
        int r0 = wid * 16;
        wmma::fragment<wmma::accumulator, 16, 16, 8, float> oacc[2];
        wmma::fill_fragment(oacc[0], 0.f);
        wmma::fill_fragment(oacc[1], 0.f);
#pragma unroll
        for (int kk = 0; kk < 16; kk++) {
            wmma::fragment<wmma::matrix_a, 16, 16, 8, wmma::precision::tf32, wmma::row_major> af;
            wmma::fragment<wmma::matrix_b, 16, 16, 8, wmma::precision::tf32, wmma::row_major> bf0, bf1;
            wmma::load_matrix_sync(af, &Hs[r0 * 132 + kk * 8], 132);
            wmma::load_matrix_sync(bf0, &W1s[kk * 8 * 36], 36);
            wmma::load_matrix_sync(bf1, &W1s[kk * 8 * 36 + 16], 36);
            wmma::mma_sync(oacc[0], af, bf0, oacc[0]);
            wmma::mma_sync(oacc[1], af, bf1, oacc[1]);
        }
        float* dst = g_part + (size_t)p * MROWS * 32 + (size_t)(m0 + r0) * 32;
        wmma::store_matrix_sync(dst, oacc[0], 32, wmma::mem_row_major);
        wmma::store_matrix_sync(dst + 16, oacc[1], 32, wmma::mem_row_major);
    }
}

// ---------------------------------------------------------------------------
// STAGE2 (combine fused) — unchanged from round 9.
// ---------------------------------------------------------------------------
struct WPtrs { const float* p[20]; };

#define WTOT    8820
#define WARPTMP 1008

__global__ void __launch_bounds__(256) stage2_kernel(
    const float* __restrict__ tokG, const void* __restrict__ invG,
    const float* __restrict__ rdiff, WPtrs wp,
    const float* __restrict__ rd0w_, const float* __restrict__ rd0b_,
    const float* __restrict__ rd1w_, const float* __restrict__ rd1b_,
    const float* __restrict__ b1_, float* __restrict__ out)
{
    extern __shared__ float sm[];
    const int tid = threadIdx.x, wid = tid >> 5, lane = tid & 31;

    const int srcidx[19] = {0,1,2,3,5,6,7,8,9,10,11,12,13,14,15,16,17,18,19};
    const int cnt[19] = {128,8,8,1,64,2048,32,1024,32,1056,33,1024,32,32,1,2080,32,512,16};
    const int off[19] = {0,128,136,144,145,209,2257,2289,3313,3345,4401,4434,5458,5490,5522,5523,7603,7635,8147};
    for (int s = 0; s < 19; s++) {
        const float* src = wp.p[srcidx[s]]; float* dst = sm + off[s];
        for (int i = tid; i < cnt[s]; i += 256) dst[i] = src[i];
    }
    for (int i = tid; i < 64;  i += 256) sm[8163 + i] = rd0w_[i];
    for (int i = tid; i < 16;  i += 256) sm[8227 + i] = rd0b_[i];
    for (int i = tid; i < 512; i += 256) sm[8243 + i] = rd1w_[i];
    for (int i = tid; i < 32;  i += 256) sm[8755 + i] = rd1b_[i];
    for (int i = tid; i < 32;  i += 256) sm[8787 + i] = b1_[i];
    __syncthreads();

    const float* nr0w = sm;          const float* nr0b = sm + 128;
    const float* nr1w = sm + 136;    const float* nr1b = sm + 144;
    const float* bf0wg = wp.p[4];    // GLOBAL
    const float* bf0b = sm + 145;
    const float* bf1w = sm + 209;    const float* bf1b = sm + 2257;
    const float* vf0w = sm + 2289;   const float* vf0b = sm + 3313;
    const float* vf1w = sm + 3345;   const float* vf1b = sm + 4401;
    const float* v20w = sm + 4434;   const float* v20b = sm + 5458;
    const float* v21w = sm + 5490;   const float* v21b = sm + 5522;
    const float* gf0w = sm + 5523;   const float* gf0b = sm + 7603;
    const float* gf1w = sm + 7635;   const float* gf1b = sm + 8147;
    const float* rd0w = sm + 8163;   const float* rd0b = sm + 8227;
    const float* rd1w = sm + 8243;   const float* rd1b = sm + 8755;
    const float* b1s  = sm + 8787;

    float* T = sm + WTOT + wid * WARPTMP;
    float* tokW = T;         float* bottW = T + 128;  float* xW   = T + 384;
    float* gfW  = T + 640;   float* h64W  = T + 768;  float* h33e = T + 896;
    float* h33o = T + 932;   float* wtW   = T + 968;  float* w0W  = T + 976;
    float* mskW = T + 984;   float* visW  = T + 992;  float* w2W  = T + 1000;

    int t = blockIdx.x * 8 + wid;

    const unsigned char* bb = (const unsigned char*)invG;
    int u8f = 0;
    for (int i = lane; i < 256; i += 32) if ((i & 3) && bb[i] == 1) u8f = 1;
    u8f = (__ballot_sync(0xffffffffu, u8f) != 0);

    for (int i = lane; i < 128; i += 32) tokW[i] = tokG[(size_t)t * 128 + i];
    float mv = 0.f;
    if (lane < 8) {
        int idx = t * 8 + lane;
        bool inv = u8f ? (bb[idx] != 0)
                       : (((const unsigned int*)invG)[idx] != 0u);
        mv = inv ? 0.f : 1.f;
    }
    float msum = wrsum(mv);
    if (lane < 8) { mskW[lane] = mv; wtW[lane] = mv / (msum + 1e-8f); }

#pragma unroll
    for (int vp = 0; vp < 4; vp++) {
        size_t rA = (size_t)t * 8 + 2 * vp, rB = rA + 1;
        float rvA = (lane < 4) ? rdiff[rA * 4 + lane] : 0.f;
        float rvB = (lane < 4) ? rdiff[rB * 4 + lane] : 0.f;
        float a0 = __shfl_sync(0xffffffffu, rvA, 0), a1 = __shfl_sync(0xffffffffu, rvA, 1);
        float a2 = __shfl_sync(0xffffffffu, rvA, 2), a3 = __shfl_sync(0xffffffffu, rvA, 3);
        float c0 = __shfl_sync(0xffffffffu, rvB, 0), c1 = __shfl_sync(0xffffffffu, rvB, 1);
        float c2 = __shfl_sync(0xffffffffu, rvB, 2), c3 = __shfl_sync(0xffffffffu, rvB, 3);
        float h0 = 0.f, h1 = 0.f;
        if (lane < 16) {
            h0 = eluf(rd0b[lane] + a0 * rd0w[lane] + a1 * rd0w[16 + lane]
                                 + a2 * rd0w[32 + lane] + a3 * rd0w[48 + lane]);
            h1 = eluf(rd0b[lane] + c0 * rd0w[lane] + c1 * rd0w[16 + lane]
                                 + c2 * rd0w[32 + lane] + c3 * rd0w[48 + lane]);
        }
        float d0 = rd1b[lane], d1 = rd1b[lane];
#pragma unroll
        for (int k = 0; k < 16; k++) {
            float w = rd1w[k * 32 + lane];
            d0 += __shfl_sync(0xffffffffu, h0, k) * w;
            d1 += __shfl_sync(0xffffffffu, h1, k) * w;
        }
        float s0 = b1s[lane] + eluf(d0), s1 = b1s[lane] + eluf(d1);
#pragma unroll
        for (int p = 0; p < 4; p++) {
            s0 += g_part[(size_t)p * MROWS * 32 + rA * 32 + lane];
            s1 += g_part[(size_t)p * MROWS * 32 + rB * 32 + lane];
        }
        bottW[2 * vp * 32 + lane] = s0;
        bottW[(2 * vp + 1) * 32 + lane] = s1;
    }
    __syncwarp();

    if (lane < 8) {
        float hh[8];
#pragma unroll
        for (int i = 0; i < 8; i++) hh[i] = nr0b[i];
#pragma unroll
        for (int k = 0; k < 16; k++) {
            float tv = tokW[lane * 16 + k];
#pragma unroll
            for (int i = 0; i < 8; i++) hh[i] += tv * nr0w[k * 8 + i];
        }
        float s = nr1b[0];
#pragma unroll
        for (int i = 0; i < 8; i++) s += eluf(hh[i]) * nr1w[i];
        w0W[lane] = sigm(s) * wtW[lane];
    }
    __syncwarp();

    {
        float m0 = 0.f, m1 = 0.f;
#pragma unroll
        for (int v = 0; v < 8; v++) { float b = bottW[v * 32 + lane]; m0 += b * w0W[v]; m1 += b * wtW[v]; }
        float v0 = 0.f, v1 = 0.f;
#pragma unroll
        for (int v = 0; v < 8; v++) {
            float b = bottW[v * 32 + lane]; float d0 = b - m0, d1 = b - m1;
            v0 += w0W[v] * d0 * d0; v1 += wtW[v] * d1 * d1;
        }
        gfW[lane] = m0; gfW[32 + lane] = v0; gfW[64 + lane] = m1; gfW[96 + lane] = v1;
    }
    __syncwarp();

    float gfc0 = bf0b[lane], gfc1 = bf0b[32 + lane];
#pragma unroll
    for (int k4 = 0; k4 < 32; k4++) {
        float4 g4 = *(float4*)&gfW[k4 * 4];
#pragma unroll
        for (int e = 0; e < 4; e++) {
            int k = k4 * 4 + e;
            float g = (&g4.x)[e];
            gfc0 += g * __ldg(&bf0wg[k * 64 + lane]);
            gfc1 += g * __ldg(&bf0wg[k * 64 + 32 + lane]);
        }
    }

#pragma unroll 1
    for (int vp = 0; vp < 4; vp++) {
        const int v0 = 2 * vp, v1 = v0 + 1;
        {
            float a00 = gfc0, a01 = gfc1, a10 = gfc0, a11 = gfc1;
#pragma unroll
            for (int k4 = 0; k4 < 8; k4++) {
                float4 bA = *(float4*)&bottW[v0 * 32 + k4 * 4];
                float4 bB = *(float4*)&bottW[v1 * 32 + k4 * 4];
#pragma unroll
                for (int e = 0; e < 4; e++) {
                    int k = k4 * 4 + e;
                    float w0 = __ldg(&bf0wg[(128 + k) * 64 + lane]);
                    float w1 = __ldg(&bf0wg[(128 + k) * 64 + 32 + lane]);
                    float fA = (&bA.x)[e], fB = (&bB.x)[e];
                    a00 += fA * w0; a01 += fA * w1;
                    a10 += fB * w0; a11 += fB * w1;
                }
            }
#pragma unroll
            for (int k4 = 0; k4 < 4; k4++) {
                float4 tA = *(float4*)&tokW[v0 * 16 + k4 * 4];
                float4 tB = *(float4*)&tokW[v1 * 16 + k4 * 4];
#pragma unroll
                for (int e = 0; e < 4; e++) {
                    int k = k4 * 4 + e;
                    float w0 = __ldg(&bf0wg[(160 + k) * 64 + lane]);
                    float w1 = __ldg(&bf0wg[(160 + k) * 64 + 32 + lane]);
                    float fA = (&tA.x)[e], fB = (&tB.x)[e];
                    a00 += fA * w0; a01 += fA * w1;
                    a10 += fB * w0; a11 += fB * w1;
                }
            }
            h64W[lane] = eluf(a00); h64W[32 + lane] = eluf(a01);
            h64W[64 + lane] = eluf(a10); h64W[96 + lane] = eluf(a11);
        }
        __syncwarp();
        {
            float s0 = bf1b[lane], s1 = bf1b[lane];
#pragma unroll
            for (int k4 = 0; k4 < 16; k4++) {
                float4 hA = *(float4*)&h64W[k4 * 4];
                float4 hB = *(float4*)&h64W[64 + k4 * 4];
#pragma unroll
                for (int e = 0; e < 4; e++) {
                    float w = bf1w[(k4 * 4 + e) * 32 + lane];
                    s0 += (&hA.x)[e] * w; s1 += (&hB.x)[e] * w;
                }
            }
            xW[v0 * 32 + lane] = eluf(s0);
            xW[v1 * 32 + lane] = eluf(s1);
        }
        __syncwarp();
        const float wv0 = wtW[v0], wv1 = wtW[v1];
        {
            float dot0 = 0.f, dot1 = 0.f;
#pragma unroll
            for (int k4 = 0; k4 < 8; k4++) {
                float4 xA = *(float4*)&xW[v0 * 32 + k4 * 4];
                float4 xB = *(float4*)&xW[v1 * 32 + k4 * 4];
#pragma unroll
                for (int e = 0; e < 4; e++) {
                    float w = vf0w[(k4 * 4 + e) * 32 + lane];
                    dot0 += (&xA.x)[e] * w; dot1 += (&xB.x)[e] * w;
                }
            }
            h33e[lane] = eluf(vf0b[lane] + wv0 * dot0);
            h33o[lane] = eluf(vf0b[lane] + wv1 * dot1);
        }
        __syncwarp();
        float xres0, xres1;
        {
            float d0 = vf1b[lane], d1 = vf1b[lane];
#pragma unroll
            for (int k4 = 0; k4 < 8; k4++) {
                float4 hA = *(float4*)&h33e[k4 * 4];
                float4 hB = *(float4*)&h33o[k4 * 4];
#pragma unroll
                for (int e = 0; e < 4; e++) {
                    float w = vf1w[(k4 * 4 + e) * 33 + lane];
                    d0 += (&hA.x)[e] * w; d1 += (&hB.x)[e] * w;
                }
            }
            xres0 = eluf(d0); xres1 = eluf(d1);
        }
        if (lane < 2) {
            const float* hx = h33e + lane * 36;
            float a = vf1b[32];
#pragma unroll
            for (int k = 0; k < 32; k++) a += hx[k] * vf1w[k * 33 + 32];
            visW[v0 + lane] = sigm(eluf(a)) * mskW[v0 + lane];
        }
        __syncwarp();
        xW[v0 * 32 + lane] += xres0;
        xW[v1 * 32 + lane] += xres1;
        __syncwarp();
        const float vv0 = visW[v0], vv1 = visW[v1];
        {
            float dot0 = 0.f, dot1 = 0.f;
#pragma unroll
            for (int k4 = 0; k4 < 8; k4++) {
                float4 xA = *(float4*)&xW[v0 * 32 + k4 * 4];
                float4 xB = *(float4*)&xW[v1 * 32 + k4 * 4];
#pragma unroll
                for (int e = 0; e < 4; e++) {
                    float w = v20w[(k4 * 4 + e) * 32 + lane];
                    dot0 += (&xA.x)[e] * w; dot1 += (&xB.x)[e] * w;
                }
            }
            h33e[lane] = eluf(v20b[lane] + vv0 * dot0);
            h33o[lane] = eluf(v20b[lane] + vv1 * dot1);
        }
        __syncwarp();
        {
            float wv21 = v21w[lane];
            float s0 = wrsum(h33e[lane] * wv21) + v21b[0];
            float s1 = wrsum(h33o[lane] * wv21) + v21b[0];
            if (lane == 0) {
                w2W[v0] = sigm(s0) * mskW[v0];
                w2W[v1] = sigm(s1) * mskW[v1];
            }
        }
        __syncwarp();
    }

    {
        float vv = (lane < 8) ? w2W[lane] : 0.f;
        float s = wrsum(vv);
        if (lane < 8) w2W[lane] = vv / (s + 1e-8f);
    }
    __syncwarp();
    float wbar;
    {
        float vv = (lane < 8) ? w2W[lane] : 0.f;
        wbar = wrsum(vv) * 0.125f;
    }
    {
        float m = 0.f;
#pragma unroll
        for (int v = 0; v < 8; v++) m += xW[v * 32 + lane] * w2W[v];
        float va = 0.f;
#pragma unroll
        for (int v = 0; v < 8; v++) { float dd = xW[v * 32 + lane] - m; va += w2W[v] * dd * dd; }
        gfW[lane] = m; gfW[32 + lane] = va;
        if (lane == 0) gfW[64] = wbar;
    }
    __syncwarp();
    {
        float a = gf0b[lane];
#pragma unroll
        for (int k4 = 0; k4 < 16; k4++) {
            float4 g4 = *(float4*)&gfW[k4 * 4];
#pragma unroll
            for (int e = 0; e < 4; e++)
                a += (&g4.x)[e] * gf0w[(k4 * 4 + e) * 32 + lane];
        }
        a += gfW[64] * gf0w[64 * 32 + lane];
        h33e[lane] = eluf(a);
    }
    __syncwarp();
    if (lane < 16) {
        float a = gf1b[lane];
#pragma unroll
        for (int k = 0; k < 32; k++) a += h33e[k] * gf1w[k * 16 + lane];
        out[(size_t)t * 16 + lane] = eluf(a);
    }
}

// ---------------------------------------------------------------------------
extern "C" void kernel_launch(void* const* d_in, const int* in_sizes, int n_in,
                              void* d_out, int out_size)
{
    const float* tok   = (const float*)d_in[0];
    const float* bott  = (const float*)d_in[1];
    const float* rdiff = (const float*)d_in[2];
    const void*  inval = (const void*)d_in[3];
    const float* rd0w = (const float*)d_in[4];  const float* rd0b = (const float*)d_in[5];
    const float* rd1w = (const float*)d_in[6];  const float* rd1b = (const float*)d_in[7];
    const float* if0w = (const float*)d_in[8];  const float* if0b = (const float*)d_in[9];
    const float* if1w = (const float*)d_in[10]; const float* if1b = (const float*)d_in[11];
    float* out = (float*)d_out;

    WPtrs wp;
    for (int i = 0; i < 20; i++) wp.p[i] = (const float*)d_in[12 + i];

    const int stage2_smem = (WTOT + 8 * WARPTMP) * 4;   // 67536 B
    cudaFuncSetAttribute(gemm1_kernel, cudaFuncAttributeMaxDynamicSharedMemorySize, SMEM_G1);
    cudaFuncSetAttribute(stage2_kernel, cudaFuncAttributeMaxDynamicSharedMemorySize, stage2_smem);

    prep_w0t<<<dim3(16, 64), dim3(32, 8)>>>(if0w);
    gemm1_kernel<<<4096, 256, SMEM_G1>>>(bott, if0b, if1w, if0w);
    stage2_kernel<<<TOTPTS / 8, 256, stage2_smem>>>(tok, inval, rdiff, wp,
                                                    rd0w, rd0b, rd1w, rd1b, if1b, out);
}

// round 11
// speedup vs baseline: 1.3380x; 1.3380x over previous
#include <cuda_runtime.h>
#include <mma.h>
#include <math.h>
#include <stdint.h>

using namespace nvcuda;

#define TOTPTS 16384
#define MROWS  131072   // TOT*NV
#define KDIM   2048
#define NDIM   512

// Static device scratch (no runtime allocation allowed).
__device__ float g_W0T[(size_t)NDIM * KDIM];       // W0^T [n][k], tf32-RN, 4MB
__device__ float g_part[(size_t)4 * MROWS * 32];   // per-N-chunk partial B32, 64MB

__device__ __forceinline__ float eluf(float x) { return x > 0.f ? x : expm1f(x); }
__device__ __forceinline__ float sigm(float x) { return 1.f / (1.f + expf(-x)); }
__device__ __forceinline__ float wrsum(float v) {
#pragma unroll
    for (int o = 16; o > 0; o >>= 1) v += __shfl_xor_sync(0xffffffffu, v, o);
    return v;
}
__device__ __forceinline__ float rnd_tf32(float x) {
    float r;
    asm("cvt.rna.tf32.f32 %0, %1;" : "=f"(r) : "f"(x));
    return r;
}
__device__ __forceinline__ uint32_t smem_u32(const void* p) {
    uint32_t a;
    asm("{ .reg .u64 t; cvta.to.shared.u64 t, %1; cvt.u32.u64 %0, t; }" : "=r"(a) : "l"(p));
    return a;
}
__device__ __forceinline__ void bulkcp(uint32_t dst, const void* src, uint32_t bytes,
                                       uint32_t bar) {
    asm volatile("cp.async.bulk.shared::cta.global.mbarrier::complete_tx::bytes "
                 "[%0], [%1], %2, [%3];"
                 :: "r"(dst), "l"(src), "r"(bytes), "r"(bar) : "memory");
}
__device__ __forceinline__ void ldsm4(uint32_t& r0, uint32_t& r1, uint32_t& r2, uint32_t& r3,
                                      uint32_t addr) {
    asm volatile("ldmatrix.sync.aligned.m8n8.x4.shared.b16 {%0,%1,%2,%3}, [%4];"
                 : "=r"(r0), "=r"(r1), "=r"(r2), "=r"(r3) : "r"(addr));
}
__device__ __forceinline__ void mma8(float* d, const uint32_t* a, const uint32_t* b) {
    asm volatile("mma.sync.aligned.m16n8k8.row.col.f32.tf32.tf32.f32 "
                 "{%0,%1,%2,%3}, {%4,%5,%6,%7}, {%8,%9}, {%0,%1,%2,%3};"
                 : "+f"(d[0]), "+f"(d[1]), "+f"(d[2]), "+f"(d[3])
                 : "r"(a[0]), "r"(a[1]), "r"(a[2]), "r"(a[3]), "r"(b[0]), "r"(b[1]));
}
#define MBAR_INIT(a, c) asm volatile("mbarrier.init.shared.b64 [%0], %1;" :: "r"(a), "r"(c) : "memory")
#define MBAR_EXPECT(a, tx) asm volatile("mbarrier.arrive.expect_tx.shared.b64 _, [%0], %1;" :: "r"(a), "r"(tx) : "memory")
#define MBAR_WAIT(a, ph) do {                                                              \
    uint32_t _m = (a), _p = (ph), _d;                                                      \
    asm volatile("{\n\t.reg .pred p;\n\t"                                                  \
                 "mbarrier.try_wait.parity.acquire.cta.shared::cta.b64 p, [%1], %2;\n\t"   \
                 "selp.b32 %0, 1, 0, p;\n\t}" : "=r"(_d) : "r"(_m), "r"(_p) : "memory");   \
    if (!_d) {                                                                             \
        asm volatile("{\n\t.reg .pred P1;\n\t"                                             \
            "WL%=:\n\t"                                                                    \
            "mbarrier.try_wait.parity.acquire.cta.shared::cta.b64 P1, [%0], %1, 0x989680;\n\t" \
            "@P1 bra.uni WD%=;\n\t"                                                        \
            "bra.uni WL%=;\n\t"                                                            \
            "WD%=:\n\t}" :: "r"(_m), "r"(_p) : "memory");                                  \
    }                                                                                      \
} while (0)
#define FENCE_PROXY() asm volatile("fence.proxy.async.shared::cta;" ::: "memory")

// ---------------------------------------------------------------------------
// PREP: g_W0T[n][k] = rn_tf32(W0[k][n])
// ---------------------------------------------------------------------------
__global__ void prep_w0t(const float* __restrict__ W0) {
    __shared__ float tile[32][33];
    int n0 = blockIdx.x * 32, k0 = blockIdx.y * 32;
    int tx = threadIdx.x, ty = threadIdx.y;
#pragma unroll
    for (int j = 0; j < 32; j += 8)
        tile[ty + j][tx] = W0[(size_t)(k0 + ty + j) * NDIM + n0 + tx];
    __syncthreads();
#pragma unroll
    for (int j = 0; j < 32; j += 8)
        g_W0T[(size_t)(n0 + ty + j) * KDIM + k0 + tx] = rnd_tf32(tile[tx][ty + j]);
}

// ---------------------------------------------------------------------------
// GEMM1 (round-8/9 tensor path — at legacy tensor-pipe ceiling; unchanged).
// ---------------------------------------------------------------------------
#define STAGEB   36864
#define SMEM_G1  88064
#define HS_F     256
#define W1S_F    17152

__global__ void __launch_bounds__(256, 2) gemm1_kernel(
    const float* __restrict__ X, const float* __restrict__ b0,
    const float* __restrict__ W1)
{
    extern __shared__ float sm[];
    const uint32_t smem = smem_u32(sm);
    const int tid = threadIdx.x, wid = tid >> 5, lane = tid & 31;
    const int p = blockIdx.x, m0 = blockIdx.y * 128, n0 = p * 128;
    const int wm = (wid >> 2) * 64, wn = (wid & 3) * 32;

    if (tid < 128) sm[32 + tid] = b0[n0 + tid];
    if (tid == 0) {
        MBAR_INIT(smem + 16, 1);
        MBAR_INIT(smem + 24, 1);
        FENCE_PROXY();
    }
    __syncthreads();

    const bool isA = tid < 128;
    const int row = tid & 127;
    const float* srcbase = isA ? (X + (size_t)(m0 + row) * KDIM)
                               : (g_W0T + (size_t)(n0 + row) * KDIM);
    const uint32_t dsto = (isA ? 0u : 18432u) + (uint32_t)row * 144u;

    float acc[4][4][4];
#pragma unroll
    for (int g = 0; g < 4; g++)
#pragma unroll
        for (int j = 0; j < 4; j++)
#pragma unroll
            for (int e = 0; e < 4; e++) acc[g][j][e] = 0.f;

    const int rA = lane & 15, hA = (lane >> 4) & 1;
    const int rB = (lane & 7) + ((lane >> 4) & 1) * 8, hB = (lane >> 3) & 1;
    const uint32_t aoff = (uint32_t)(wm + rA) * 144u + (uint32_t)hA * 16u;
    const uint32_t boff = 18432u + (uint32_t)(wn + rB) * 144u + (uint32_t)hB * 16u;

#pragma unroll
    for (int t = 0; t < 2; t++) {
        uint32_t bar = smem + 16 + 8 * t;
        if (tid == 0) MBAR_EXPECT(bar, 32768);
        __syncwarp();
        bulkcp(smem + 1024 + t * STAGEB + dsto, srcbase + t * 32, 128, bar);
    }

    for (int t = 0; t < 64; t++) {
        const int s = t & 1;
        MBAR_WAIT(smem + 16 + 8 * s, (t >> 1) & 1);

        const uint32_t base = smem + 1024 + s * STAGEB;
#pragma unroll
        for (int ks = 0; ks < 4; ks++) {
            uint32_t a[4][4], b[2][4];
#pragma unroll
            for (int g = 0; g < 4; g++)
                ldsm4(a[g][0], a[g][1], a[g][2], a[g][3],
                      base + aoff + (uint32_t)g * 2304u + (uint32_t)ks * 32u);
#pragma unroll
            for (int jj = 0; jj < 2; jj++)
                ldsm4(b[jj][0], b[jj][1], b[jj][2], b[jj][3],
                      base + boff + (uint32_t)jj * 2304u + (uint32_t)ks * 32u);
#pragma unroll
            for (int g = 0; g < 4; g++)
#pragma unroll
                for (int e = 0; e < 4; e++)
                    a[g][e] = __float_as_uint(rnd_tf32(__uint_as_float(a[g][e])));
#pragma unroll
            for (int g = 0; g < 4; g++) {
                mma8(acc[g][0], a[g], &b[0][0]);
                mma8(acc[g][1], a[g], &b[0][2]);
                mma8(acc[g][2], a[g], &b[1][0]);
                mma8(acc[g][3], a[g], &b[1][2]);
            }
        }
        __syncthreads();
        if (t + 2 < 64) {
            uint32_t bar = smem + 16 + 8 * s;
            if (tid == 0) MBAR_EXPECT(bar, 32768);
            bulkcp(smem + 1024 + s * STAGEB + dsto, srcbase + (t + 2) * 32, 128, bar);
        }
    }

    float* Hs  = sm + HS_F;
    float* W1s = sm + W1S_F;
    {
        const int tr = lane >> 2, tc = 2 * (lane & 3);
#pragma unroll
        for (int g = 0; g < 4; g++)
#pragma unroll
            for (int j = 0; j < 4; j++) {
                int R0 = wm + g * 16 + tr, C = wn + j * 8 + tc;
                float b0c0 = sm[32 + C], b0c1 = sm[32 + C + 1];
                float2 v0, v1;
                v0.x = rnd_tf32(eluf(acc[g][j][0] + b0c0));
                v0.y = rnd_tf32(eluf(acc[g][j][1] + b0c1));
                v1.x = rnd_tf32(eluf(acc[g][j][2] + b0c0));
                v1.y = rnd_tf32(eluf(acc[g][j][3] + b0c1));
                *(float2*)&Hs[R0 * 132 + C] = v0;
                *(float2*)&Hs[(R0 + 8) * 132 + C] = v1;
            }
    }
    for (int i = tid; i < 128 * 32; i += 256) {
        int r = i >> 5, c = i & 31;
        W1s[r * 36 + c] = rnd_tf32(W1[(size_t)(n0 + r) * 32 + c]);
    }
    __syncthreads();

    {
        int r0 = wid * 16;
        wmma::fragment<wmma::accumulator, 16, 16, 8, float> oacc[2];
        wmma::fill_fragment(oacc[0], 0.f);
        wmma::fill_fragment(oacc[1], 0.f);
#pragma unroll
        for (int kk = 0; kk < 16; kk++) {
            wmma::fragment<wmma::matrix_a, 16, 16, 8, wmma::precision::tf32, wmma::row_major> af;
            wmma::fragment<wmma::matrix_b, 16, 16, 8, wmma::precision::tf32, wmma::row_major> bf0, bf1;
            wmma::load_matrix_sync(af, &Hs[r0 * 132 + kk * 8], 132);
            wmma::load_matrix_sync(bf0, &W1s[kk * 8 * 36], 36);
            wmma::load_matrix_sync(bf1, &W1s[kk * 8 * 36 + 16], 36);
            wmma::mma_sync(oacc[0], af, bf0, oacc[0]);
            wmma::mma_sync(oacc[1], af, bf1, oacc[1]);
        }
        float* dst = g_part + (size_t)p * MROWS * 32 + (size_t)(m0 + r0) * 32;
        wmma::store_matrix_sync(dst, oacc[0], 32, wmma::mem_row_major);
        wmma::store_matrix_sync(dst + 16, oacc[1], 32, wmma::mem_row_major);
    }
}

// ---------------------------------------------------------------------------
// STAGE2 (combine fused, paired views). smem trimmed to 57.2KB -> 4 CTAs/SM:
// bf0w, gf0w, rd1w now read from GLOBAL via coalesced __ldg.
// ---------------------------------------------------------------------------
struct WPtrs { const float* p[20]; };

#define WTOT    6228
#define WARPTMP 1008

__global__ void __launch_bounds__(256) stage2_kernel(
    const float* __restrict__ tokG, const void* __restrict__ invG,
    const float* __restrict__ rdiff, WPtrs wp,
    const float* __restrict__ rd0w_, const float* __restrict__ rd0b_,
    const float* __restrict__ rd1w_, const float* __restrict__ rd1b_,
    const float* __restrict__ b1_, float* __restrict__ out)
{
    extern __shared__ float sm[];
    const int tid = threadIdx.x, wid = tid >> 5, lane = tid & 31;

    // weights -> smem (bf0w, gf0w excluded; stay global)
    const int srcidx[18] = {0,1,2,3,5,6,7,8,9,10,11,12,13,14,15,17,18,19};
    const int cnt[18] = {128,8,8,1,64,2048,32,1024,32,1056,33,1024,32,32,1,32,512,16};
    const int off[18] = {0,128,136,144,145,209,2257,2289,3313,3345,4401,4434,5458,5490,5522,5523,5555,6067};
    for (int s = 0; s < 18; s++) {
        const float* src = wp.p[srcidx[s]]; float* dst = sm + off[s];
        for (int i = tid; i < cnt[s]; i += 256) dst[i] = src[i];
    }
    for (int i = tid; i < 64; i += 256) sm[6083 + i] = rd0w_[i];
    for (int i = tid; i < 16; i += 256) sm[6147 + i] = rd0b_[i];
    for (int i = tid; i < 32; i += 256) sm[6163 + i] = rd1b_[i];
    for (int i = tid; i < 32; i += 256) sm[6195 + i] = b1_[i];
    __syncthreads();

    const float* nr0w = sm;          const float* nr0b = sm + 128;
    const float* nr1w = sm + 136;    const float* nr1b = sm + 144;
    const float* bf0wg = wp.p[4];    // GLOBAL
    const float* bf0b = sm + 145;
    const float* bf1w = sm + 209;    const float* bf1b = sm + 2257;
    const float* vf0w = sm + 2289;   const float* vf0b = sm + 3313;
    const float* vf1w = sm + 3345;   const float* vf1b = sm + 4401;
    const float* v20w = sm + 4434;   const float* v20b = sm + 5458;
    const float* v21w = sm + 5490;   const float* v21b = sm + 5522;
    const float* gf0wg = wp.p[16];   // GLOBAL
    const float* gf0b = sm + 5523;
    const float* gf1w = sm + 5555;   const float* gf1b = sm + 6067;
    const float* rd0w = sm + 6083;   const float* rd0b = sm + 6147;
    const float* rd1b = sm + 6163;   const float* b1s  = sm + 6195;

    float* T = sm + WTOT + wid * WARPTMP;
    float* tokW = T;         float* bottW = T + 128;  float* xW   = T + 384;
    float* gfW  = T + 640;   float* h64W  = T + 768;  float* h33e = T + 896;
    float* h33o = T + 932;   float* wtW   = T + 968;  float* w0W  = T + 976;
    float* mskW = T + 984;   float* visW  = T + 992;  float* w2W  = T + 1000;

    int t = blockIdx.x * 8 + wid;

    // dtype-robust invalid_features read
    const unsigned char* bb = (const unsigned char*)invG;
    int u8f = 0;
    for (int i = lane; i < 256; i += 32) if ((i & 3) && bb[i] == 1) u8f = 1;
    u8f = (__ballot_sync(0xffffffffu, u8f) != 0);

    for (int i = lane; i < 128; i += 32) tokW[i] = tokG[(size_t)t * 128 + i];
    float mv = 0.f;
    if (lane < 8) {
        int idx = t * 8 + lane;
        bool inv = u8f ? (bb[idx] != 0)
                       : (((const unsigned int*)invG)[idx] != 0u);
        mv = inv ? 0.f : 1.f;
    }
    float msum = wrsum(mv);
    if (lane < 8) { mskW[lane] = mv; wtW[lane] = mv / (msum + 1e-8f); }

    // ---- fused combine: bott = sum_p part + b1 + elu(rd-MLP), paired views
#pragma unroll
    for (int vp = 0; vp < 4; vp++) {
        size_t rA = (size_t)t * 8 + 2 * vp, rB = rA + 1;
        float rvA = (lane < 4) ? rdiff[rA * 4 + lane] : 0.f;
        float rvB = (lane < 4) ? rdiff[rB * 4 + lane] : 0.f;
        float a0 = __shfl_sync(0xffffffffu, rvA, 0), a1 = __shfl_sync(0xffffffffu, rvA, 1);
        float a2 = __shfl_sync(0xffffffffu, rvA, 2), a3 = __shfl_sync(0xffffffffu, rvA, 3);
        float c0 = __shfl_sync(0xffffffffu, rvB, 0), c1 = __shfl_sync(0xffffffffu, rvB, 1);
        float c2 = __shfl_sync(0xffffffffu, rvB, 2), c3 = __shfl_sync(0xffffffffu, rvB, 3);
        float h0 = 0.f, h1 = 0.f;
        if (lane < 16) {
            h0 = eluf(rd0b[lane] + a0 * rd0w[lane] + a1 * rd0w[16 + lane]
                                 + a2 * rd0w[32 + lane] + a3 * rd0w[48 + lane]);
            h1 = eluf(rd0b[lane] + c0 * rd0w[lane] + c1 * rd0w[16 + lane]
                                 + c2 * rd0w[32 + lane] + c3 * rd0w[48 + lane]);
        }
        float d0 = rd1b[lane], d1 = rd1b[lane];
#pragma unroll
        for (int k = 0; k < 16; k++) {
            float w = __ldg(&rd1w_[k * 32 + lane]);
            d0 += __shfl_sync(0xffffffffu, h0, k) * w;
            d1 += __shfl_sync(0xffffffffu, h1, k) * w;
        }
        float s0 = b1s[lane] + eluf(d0), s1 = b1s[lane] + eluf(d1);
#pragma unroll
        for (int p = 0; p < 4; p++) {
            s0 += g_part[(size_t)p * MROWS * 32 + rA * 32 + lane];
            s1 += g_part[(size_t)p * MROWS * 32 + rB * 32 + lane];
        }
        bottW[2 * vp * 32 + lane] = s0;
        bottW[(2 * vp + 1) * 32 + lane] = s1;
    }
    __syncwarp();

    // nr: 16 -> 8 (elu) -> 1, sigmoid, * weight
    if (lane < 8) {
        float hh[8];
#pragma unroll
        for (int i = 0; i < 8; i++) hh[i] = nr0b[i];
#pragma unroll
        for (int k = 0; k < 16; k++) {
            float tv = tokW[lane * 16 + k];
#pragma unroll
            for (int i = 0; i < 8; i++) hh[i] += tv * nr0w[k * 8 + i];
        }
        float s = nr1b[0];
#pragma unroll
        for (int i = 0; i < 8; i++) s += eluf(hh[i]) * nr1w[i];
        w0W[lane] = sigm(s) * wtW[lane];
    }
    __syncwarp();

    // weighted mean/var of bott
    {
        float m0 = 0.f, m1 = 0.f;
#pragma unroll
        for (int v = 0; v < 8; v++) { float b = bottW[v * 32 + lane]; m0 += b * w0W[v]; m1 += b * wtW[v]; }
        float v0 = 0.f, v1 = 0.f;
#pragma unroll
        for (int v = 0; v < 8; v++) {
            float b = bottW[v * 32 + lane]; float d0 = b - m0, d1 = b - m1;
            v0 += w0W[v] * d0 * d0; v1 += wtW[v] * d1 * d1;
        }
        gfW[lane] = m0; gfW[32 + lane] = v0; gfW[64 + lane] = m1; gfW[96 + lane] = v1;
    }
    __syncwarp();

    // hoisted globalfeat half of bf0 (float4 broadcasts of gfW)
    float gfc0 = bf0b[lane], gfc1 = bf0b[32 + lane];
#pragma unroll
    for (int k4 = 0; k4 < 32; k4++) {
        float4 g4 = *(float4*)&gfW[k4 * 4];
#pragma unroll
        for (int e = 0; e < 4; e++) {
            int k = k4 * 4 + e;
            float g = (&g4.x)[e];
            gfc0 += g * __ldg(&bf0wg[k * 64 + lane]);
            gfc1 += g * __ldg(&bf0wg[k * 64 + 32 + lane]);
        }
    }

    // ---- paired view loop ----
#pragma unroll 1
    for (int vp = 0; vp < 4; vp++) {
        const int v0 = 2 * vp, v1 = v0 + 1;
        // bf0 per-view part: 48 inputs -> 64 (elu), weights shared
        {
            float a00 = gfc0, a01 = gfc1, a10 = gfc0, a11 = gfc1;
#pragma unroll
            for (int k4 = 0; k4 < 8; k4++) {
                float4 bA = *(float4*)&bottW[v0 * 32 + k4 * 4];
                float4 bB = *(float4*)&bottW[v1 * 32 + k4 * 4];
#pragma unroll
                for (int e = 0; e < 4; e++) {
                    int k = k4 * 4 + e;
                    float w0 = __ldg(&bf0wg[(128 + k) * 64 + lane]);
                    float w1 = __ldg(&bf0wg[(128 + k) * 64 + 32 + lane]);
                    float fA = (&bA.x)[e], fB = (&bB.x)[e];
                    a00 += fA * w0; a01 += fA * w1;
                    a10 += fB * w0; a11 += fB * w1;
                }
            }
#pragma unroll
            for (int k4 = 0; k4 < 4; k4++) {
                float4 tA = *(float4*)&tokW[v0 * 16 + k4 * 4];
                float4 tB = *(float4*)&tokW[v1 * 16 + k4 * 4];
#pragma unroll
                for (int e = 0; e < 4; e++) {
                    int k = k4 * 4 + e;
                    float w0 = __ldg(&bf0wg[(160 + k) * 64 + lane]);
                    float w1 = __ldg(&bf0wg[(160 + k) * 64 + 32 + lane]);
                    float fA = (&tA.x)[e], fB = (&tB.x)[e];
                    a00 += fA * w0; a01 += fA * w1;
                    a10 += fB * w0; a11 += fB * w1;
                }
            }
            h64W[lane] = eluf(a00); h64W[32 + lane] = eluf(a01);
            h64W[64 + lane] = eluf(a10); h64W[96 + lane] = eluf(a11);
        }
        __syncwarp();
        // bf1: 64 -> 32 (elu), weights shared
        {
            float s0 = bf1b[lane], s1 = bf1b[lane];
#pragma unroll
            for (int k4 = 0; k4 < 16; k4++) {
                float4 hA = *(float4*)&h64W[k4 * 4];
                float4 hB = *(float4*)&h64W[64 + k4 * 4];
#pragma unroll
                for (int e = 0; e < 4; e++) {
                    float w = bf1w[(k4 * 4 + e) * 32 + lane];
                    s0 += (&hA.x)[e] * w; s1 += (&hB.x)[e] * w;
                }
            }
            xW[v0 * 32 + lane] = eluf(s0);
            xW[v1 * 32 + lane] = eluf(s1);
        }
        __syncwarp();
        // vf0 on x*weight (factor wv out of the dot)
        const float wv0 = wtW[v0], wv1 = wtW[v1];
        {
            float dot0 = 0.f, dot1 = 0.f;
#pragma unroll
            for (int k4 = 0; k4 < 8; k4++) {
                float4 xA = *(float4*)&xW[v0 * 32 + k4 * 4];
                float4 xB = *(float4*)&xW[v1 * 32 + k4 * 4];
#pragma unroll
                for (int e = 0; e < 4; e++) {
                    float w = vf0w[(k4 * 4 + e) * 32 + lane];
                    dot0 += (&xA.x)[e] * w; dot1 += (&xB.x)[e] * w;
                }
            }
            h33e[lane] = eluf(vf0b[lane] + wv0 * dot0);
            h33o[lane] = eluf(vf0b[lane] + wv1 * dot1);
        }
        __syncwarp();
        // vf1: 32 -> 33 (elu); col 32 handled by lanes 0,1
        float xres0, xres1;
        {
            float d0 = vf1b[lane], d1 = vf1b[lane];
#pragma unroll
            for (int k4 = 0; k4 < 8; k4++) {
                float4 hA = *(float4*)&h33e[k4 * 4];
                float4 hB = *(float4*)&h33o[k4 * 4];
#pragma unroll
                for (int e = 0; e < 4; e++) {
                    float w = vf1w[(k4 * 4 + e) * 33 + lane];
                    d0 += (&hA.x)[e] * w; d1 += (&hB.x)[e] * w;
                }
            }
            xres0 = eluf(d0); xres1 = eluf(d1);
        }
        if (lane < 2) {
            const float* hx = h33e + lane * 36;
            float a = vf1b[32];
#pragma unroll
            for (int k = 0; k < 32; k++) a += hx[k] * vf1w[k * 33 + 32];
            visW[v0 + lane] = sigm(eluf(a)) * mskW[v0 + lane];
        }
        __syncwarp();
        xW[v0 * 32 + lane] += xres0;
        xW[v1 * 32 + lane] += xres1;
        __syncwarp();
        // v20 on x*vis
        const float vv0 = visW[v0], vv1 = visW[v1];
        {
            float dot0 = 0.f, dot1 = 0.f;
#pragma unroll
            for (int k4 = 0; k4 < 8; k4++) {
                float4 xA = *(float4*)&xW[v0 * 32 + k4 * 4];
                float4 xB = *(float4*)&xW[v1 * 32 + k4 * 4];
#pragma unroll
                for (int e = 0; e < 4; e++) {
                    float w = v20w[(k4 * 4 + e) * 32 + lane];
                    dot0 += (&xA.x)[e] * w; dot1 += (&xB.x)[e] * w;
                }
            }
            h33e[lane] = eluf(v20b[lane] + vv0 * dot0);
            h33o[lane] = eluf(v20b[lane] + vv1 * dot1);
        }
        __syncwarp();
        {
            float wv21 = v21w[lane];
            float s0 = wrsum(h33e[lane] * wv21) + v21b[0];
            float s1 = wrsum(h33o[lane] * wv21) + v21b[0];
            if (lane == 0) {
                w2W[v0] = sigm(s0) * mskW[v0];
                w2W[v1] = sigm(s1) * mskW[v1];
            }
        }
        __syncwarp();
    }

    // weight2 normalize + wbar
    {
        float vv = (lane < 8) ? w2W[lane] : 0.f;
        float s = wrsum(vv);
        if (lane < 8) w2W[lane] = vv / (s + 1e-8f);
    }
    __syncwarp();
    float wbar;
    {
        float vv = (lane < 8) ? w2W[lane] : 0.f;
        wbar = wrsum(vv) * 0.125f;
    }
    // weighted mean/var of x
    {
        float m = 0.f;
#pragma unroll
        for (int v = 0; v < 8; v++) m += xW[v * 32 + lane] * w2W[v];
        float va = 0.f;
#pragma unroll
        for (int v = 0; v < 8; v++) { float dd = xW[v * 32 + lane] - m; va += w2W[v] * dd * dd; }
        gfW[lane] = m; gfW[32 + lane] = va;
        if (lane == 0) gfW[64] = wbar;
    }
    __syncwarp();
    // gf: 65 -> 32 (elu) -> 16 (elu)   (gf0w from GLOBAL)
    {
        float a = gf0b[lane];
#pragma unroll
        for (int k4 = 0; k4 < 16; k4++) {
            float4 g4 = *(float4*)&gfW[k4 * 4];
#pragma unroll
            for (int e = 0; e < 4; e++)
                a += (&g4.x)[e] * __ldg(&gf0wg[(k4 * 4 + e) * 32 + lane]);
        }
        a += gfW[64] * __ldg(&gf0wg[64 * 32 + lane]);
        h33e[lane] = eluf(a);
    }
    __syncwarp();
    if (lane < 16) {
        float a = gf1b[lane];
#pragma unroll
        for (int k = 0; k < 32; k++) a += h33e[k] * gf1w[k * 16 + lane];
        out[(size_t)t * 16 + lane] = eluf(a);
    }
}

// ---------------------------------------------------------------------------
extern "C" void kernel_launch(void* const* d_in, const int* in_sizes, int n_in,
                              void* d_out, int out_size)
{
    const float* tok   = (const float*)d_in[0];
    const float* bott  = (const float*)d_in[1];
    const float* rdiff = (const float*)d_in[2];
    const void*  inval = (const void*)d_in[3];
    const float* rd0w = (const float*)d_in[4];  const float* rd0b = (const float*)d_in[5];
    const float* rd1w = (const float*)d_in[6];  const float* rd1b = (const float*)d_in[7];
    const float* if0w = (const float*)d_in[8];  const float* if0b = (const float*)d_in[9];
    const float* if1w = (const float*)d_in[10]; const float* if1b = (const float*)d_in[11];
    float* out = (float*)d_out;

    WPtrs wp;
    for (int i = 0; i < 20; i++) wp.p[i] = (const float*)d_in[12 + i];

    const int stage2_smem = (WTOT + 8 * WARPTMP) * 4;   // 57168 B -> 4 CTAs/SM
    cudaFuncSetAttribute(gemm1_kernel, cudaFuncAttributeMaxDynamicSharedMemorySize, SMEM_G1);
    cudaFuncSetAttribute(stage2_kernel, cudaFuncAttributeMaxDynamicSharedMemorySize, stage2_smem);

    prep_w0t<<<dim3(16, 64), dim3(32, 8)>>>(if0w);
    gemm1_kernel<<<dim3(4, 1024), 256, SMEM_G1>>>(bott, if0b, if1w);
    stage2_kernel<<<TOTPTS / 8, 256, stage2_smem>>>(tok, inval, rdiff, wp,
                                                    rd0w, rd0b, rd1w, rd1b, if1b, out);
}

// round 12
// speedup vs baseline: 1.3457x; 1.0057x over previous
#include <cuda_runtime.h>
#include <mma.h>
#include <math.h>
#include <stdint.h>

using namespace nvcuda;

#define TOTPTS 16384
#define MROWS  131072   // TOT*NV
#define KDIM   2048
#define NDIM   512

// Static device scratch (no runtime allocation allowed).
__device__ float g_W0T[(size_t)NDIM * KDIM];       // W0^T [n][k], tf32-RN, 4MB
__device__ float g_part[(size_t)4 * MROWS * 32];   // per-N-chunk partial B32, 64MB

__device__ __forceinline__ float eluf(float x) { return x > 0.f ? x : expm1f(x); }
__device__ __forceinline__ float sigm(float x) { return 1.f / (1.f + expf(-x)); }
__device__ __forceinline__ float wrsum(float v) {
#pragma unroll
    for (int o = 16; o > 0; o >>= 1) v += __shfl_xor_sync(0xffffffffu, v, o);
    return v;
}
__device__ __forceinline__ float rnd_tf32(float x) {
    float r;
    asm("cvt.rna.tf32.f32 %0, %1;" : "=f"(r) : "f"(x));
    return r;
}
__device__ __forceinline__ uint32_t smem_u32(const void* p) {
    uint32_t a;
    asm("{ .reg .u64 t; cvta.to.shared.u64 t, %1; cvt.u32.u64 %0, t; }" : "=r"(a) : "l"(p));
    return a;
}
__device__ __forceinline__ void bulkcp(uint32_t dst, const void* src, uint32_t bytes,
                                       uint32_t bar) {
    asm volatile("cp.async.bulk.shared::cta.global.mbarrier::complete_tx::bytes "
                 "[%0], [%1], %2, [%3];"
                 :: "r"(dst), "l"(src), "r"(bytes), "r"(bar) : "memory");
}
__device__ __forceinline__ void ldsm4(uint32_t& r0, uint32_t& r1, uint32_t& r2, uint32_t& r3,
                                      uint32_t addr) {
    asm volatile("ldmatrix.sync.aligned.m8n8.x4.shared.b16 {%0,%1,%2,%3}, [%4];"
                 : "=r"(r0), "=r"(r1), "=r"(r2), "=r"(r3) : "r"(addr));
}
__device__ __forceinline__ void mma8(float* d, const uint32_t* a, const uint32_t* b) {
    asm volatile("mma.sync.aligned.m16n8k8.row.col.f32.tf32.tf32.f32 "
                 "{%0,%1,%2,%3}, {%4,%5,%6,%7}, {%8,%9}, {%0,%1,%2,%3};"
                 : "+f"(d[0]), "+f"(d[1]), "+f"(d[2]), "+f"(d[3])
                 : "r"(a[0]), "r"(a[1]), "r"(a[2]), "r"(a[3]), "r"(b[0]), "r"(b[1]));
}
#define MBAR_INIT(a, c) asm volatile("mbarrier.init.shared.b64 [%0], %1;" :: "r"(a), "r"(c) : "memory")
#define MBAR_EXPECT(a, tx) asm volatile("mbarrier.arrive.expect_tx.shared.b64 _, [%0], %1;" :: "r"(a), "r"(tx) : "memory")
#define MBAR_WAIT(a, ph) do {                                                              \
    uint32_t _m = (a), _p = (ph), _d;                                                      \
    asm volatile("{\n\t.reg .pred p;\n\t"                                                  \
                 "mbarrier.try_wait.parity.acquire.cta.shared::cta.b64 p, [%1], %2;\n\t"   \
                 "selp.b32 %0, 1, 0, p;\n\t}" : "=r"(_d) : "r"(_m), "r"(_p) : "memory");   \
    if (!_d) {                                                                             \
        asm volatile("{\n\t.reg .pred P1;\n\t"                                             \
            "WL%=:\n\t"                                                                    \
            "mbarrier.try_wait.parity.acquire.cta.shared::cta.b64 P1, [%0], %1, 0x989680;\n\t" \
            "@P1 bra.uni WD%=;\n\t"                                                        \
            "bra.uni WL%=;\n\t"                                                            \
            "WD%=:\n\t}" :: "r"(_m), "r"(_p) : "memory");                                  \
    }                                                                                      \
} while (0)
#define FENCE_PROXY() asm volatile("fence.proxy.async.shared::cta;" ::: "memory")

// ---------------------------------------------------------------------------
// PREP: g_W0T[n][k] = rn_tf32(W0[k][n])
// ---------------------------------------------------------------------------
__global__ void prep_w0t(const float* __restrict__ W0) {
    __shared__ float tile[32][33];
    int n0 = blockIdx.x * 32, k0 = blockIdx.y * 32;
    int tx = threadIdx.x, ty = threadIdx.y;
#pragma unroll
    for (int j = 0; j < 32; j += 8)
        tile[ty + j][tx] = W0[(size_t)(k0 + ty + j) * NDIM + n0 + tx];
    __syncthreads();
#pragma unroll
    for (int j = 0; j < 32; j += 8)
        g_W0T[(size_t)(n0 + ty + j) * KDIM + k0 + tx] = rnd_tf32(tile[tx][ty + j]);
}

// ---------------------------------------------------------------------------
// GEMM1 (at legacy tensor-pipe ceiling — verified rt16 model; unchanged).
// ---------------------------------------------------------------------------
#define STAGEB   36864
#define SMEM_G1  88064
#define HS_F     256
#define W1S_F    17152

__global__ void __launch_bounds__(256, 2) gemm1_kernel(
    const float* __restrict__ X, const float* __restrict__ b0,
    const float* __restrict__ W1)
{
    extern __shared__ float sm[];
    const uint32_t smem = smem_u32(sm);
    const int tid = threadIdx.x, wid = tid >> 5, lane = tid & 31;
    const int p = blockIdx.x, m0 = blockIdx.y * 128, n0 = p * 128;
    const int wm = (wid >> 2) * 64, wn = (wid & 3) * 32;

    if (tid < 128) sm[32 + tid] = b0[n0 + tid];
    if (tid == 0) {
        MBAR_INIT(smem + 16, 1);
        MBAR_INIT(smem + 24, 1);
        FENCE_PROXY();
    }
    __syncthreads();

    const bool isA = tid < 128;
    const int row = tid & 127;
    const float* srcbase = isA ? (X + (size_t)(m0 + row) * KDIM)
                               : (g_W0T + (size_t)(n0 + row) * KDIM);
    const uint32_t dsto = (isA ? 0u : 18432u) + (uint32_t)row * 144u;

    float acc[4][4][4];
#pragma unroll
    for (int g = 0; g < 4; g++)
#pragma unroll
        for (int j = 0; j < 4; j++)
#pragma unroll
            for (int e = 0; e < 4; e++) acc[g][j][e] = 0.f;

    const int rA = lane & 15, hA = (lane >> 4) & 1;
    const int rB = (lane & 7) + ((lane >> 4) & 1) * 8, hB = (lane >> 3) & 1;
    const uint32_t aoff = (uint32_t)(wm + rA) * 144u + (uint32_t)hA * 16u;
    const uint32_t boff = 18432u + (uint32_t)(wn + rB) * 144u + (uint32_t)hB * 16u;

#pragma unroll
    for (int t = 0; t < 2; t++) {
        uint32_t bar = smem + 16 + 8 * t;
        if (tid == 0) MBAR_EXPECT(bar, 32768);
        __syncwarp();
        bulkcp(smem + 1024 + t * STAGEB + dsto, srcbase + t * 32, 128, bar);
    }

    for (int t = 0; t < 64; t++) {
        const int s = t & 1;
        MBAR_WAIT(smem + 16 + 8 * s, (t >> 1) & 1);

        const uint32_t base = smem + 1024 + s * STAGEB;
#pragma unroll
        for (int ks = 0; ks < 4; ks++) {
            uint32_t a[4][4], b[2][4];
#pragma unroll
            for (int g = 0; g < 4; g++)
                ldsm4(a[g][0], a[g][1], a[g][2], a[g][3],
                      base + aoff + (uint32_t)g * 2304u + (uint32_t)ks * 32u);
#pragma unroll
            for (int jj = 0; jj < 2; jj++)
                ldsm4(b[jj][0], b[jj][1], b[jj][2], b[jj][3],
                      base + boff + (uint32_t)jj * 2304u + (uint32_t)ks * 32u);
#pragma unroll
            for (int g = 0; g < 4; g++)
#pragma unroll
                for (int e = 0; e < 4; e++)
                    a[g][e] = __float_as_uint(rnd_tf32(__uint_as_float(a[g][e])));
#pragma unroll
            for (int g = 0; g < 4; g++) {
                mma8(acc[g][0], a[g], &b[0][0]);
                mma8(acc[g][1], a[g], &b[0][2]);
                mma8(acc[g][2], a[g], &b[1][0]);
                mma8(acc[g][3], a[g], &b[1][2]);
            }
        }
        __syncthreads();
        if (t + 2 < 64) {
            uint32_t bar = smem + 16 + 8 * s;
            if (tid == 0) MBAR_EXPECT(bar, 32768);
            bulkcp(smem + 1024 + s * STAGEB + dsto, srcbase + (t + 2) * 32, 128, bar);
        }
    }

    float* Hs  = sm + HS_F;
    float* W1s = sm + W1S_F;
    {
        const int tr = lane >> 2, tc = 2 * (lane & 3);
#pragma unroll
        for (int g = 0; g < 4; g++)
#pragma unroll
            for (int j = 0; j < 4; j++) {
                int R0 = wm + g * 16 + tr, C = wn + j * 8 + tc;
                float b0c0 = sm[32 + C], b0c1 = sm[32 + C + 1];
                float2 v0, v1;
                v0.x = rnd_tf32(eluf(acc[g][j][0] + b0c0));
                v0.y = rnd_tf32(eluf(acc[g][j][1] + b0c1));
                v1.x = rnd_tf32(eluf(acc[g][j][2] + b0c0));
                v1.y = rnd_tf32(eluf(acc[g][j][3] + b0c1));
                *(float2*)&Hs[R0 * 132 + C] = v0;
                *(float2*)&Hs[(R0 + 8) * 132 + C] = v1;
            }
    }
    for (int i = tid; i < 128 * 32; i += 256) {
        int r = i >> 5, c = i & 31;
        W1s[r * 36 + c] = rnd_tf32(W1[(size_t)(n0 + r) * 32 + c]);
    }
    __syncthreads();

    {
        int r0 = wid * 16;
        wmma::fragment<wmma::accumulator, 16, 16, 8, float> oacc[2];
        wmma::fill_fragment(oacc[0], 0.f);
        wmma::fill_fragment(oacc[1], 0.f);
#pragma unroll
        for (int kk = 0; kk < 16; kk++) {
            wmma::fragment<wmma::matrix_a, 16, 16, 8, wmma::precision::tf32, wmma::row_major> af;
            wmma::fragment<wmma::matrix_b, 16, 16, 8, wmma::precision::tf32, wmma::row_major> bf0, bf1;
            wmma::load_matrix_sync(af, &Hs[r0 * 132 + kk * 8], 132);
            wmma::load_matrix_sync(bf0, &W1s[kk * 8 * 36], 36);
            wmma::load_matrix_sync(bf1, &W1s[kk * 8 * 36 + 16], 36);
            wmma::mma_sync(oacc[0], af, bf0, oacc[0]);
            wmma::mma_sync(oacc[1], af, bf1, oacc[1]);
        }
        float* dst = g_part + (size_t)p * MROWS * 32 + (size_t)(m0 + r0) * 32;
        wmma::store_matrix_sync(dst, oacc[0], 32, wmma::mem_row_major);
        wmma::store_matrix_sync(dst + 16, oacc[1], 32, wmma::mem_row_major);
    }
}

// ---------------------------------------------------------------------------
// STAGE2 v3: 4-view weight sharing — 2 super-iterations of 4 views, every
// bf0/bf1/vf0/vf1/v20 weight load serves 4 views (wavefronts/point ~-30%),
// 4 independent accumulator streams for ILP. 3 CTAs/SM (63.6KB smem).
// ---------------------------------------------------------------------------
struct WPtrs { const float* p[20]; };

#define WTOT    6228
#define WARPTMP 1208

__global__ void __launch_bounds__(256, 3) stage2_kernel(
    const float* __restrict__ tokG, const void* __restrict__ invG,
    const float* __restrict__ rdiff, WPtrs wp,
    const float* __restrict__ rd0w_, const float* __restrict__ rd0b_,
    const float* __restrict__ rd1w_, const float* __restrict__ rd1b_,
    const float* __restrict__ b1_, float* __restrict__ out)
{
    extern __shared__ float sm[];
    const int tid = threadIdx.x, wid = tid >> 5, lane = tid & 31;

    // weights -> smem (bf0w, gf0w excluded; stay global)
    const int srcidx[18] = {0,1,2,3,5,6,7,8,9,10,11,12,13,14,15,17,18,19};
    const int cnt[18] = {128,8,8,1,64,2048,32,1024,32,1056,33,1024,32,32,1,32,512,16};
    const int off[18] = {0,128,136,144,145,209,2257,2289,3313,3345,4401,4434,5458,5490,5522,5523,5555,6067};
    for (int s = 0; s < 18; s++) {
        const float* src = wp.p[srcidx[s]]; float* dst = sm + off[s];
        for (int i = tid; i < cnt[s]; i += 256) dst[i] = src[i];
    }
    for (int i = tid; i < 64; i += 256) sm[6083 + i] = rd0w_[i];
    for (int i = tid; i < 16; i += 256) sm[6147 + i] = rd0b_[i];
    for (int i = tid; i < 32; i += 256) sm[6163 + i] = rd1b_[i];
    for (int i = tid; i < 32; i += 256) sm[6195 + i] = b1_[i];
    __syncthreads();

    const float* nr0w = sm;          const float* nr0b = sm + 128;
    const float* nr1w = sm + 136;    const float* nr1b = sm + 144;
    const float* bf0wg = wp.p[4];    // GLOBAL
    const float* bf0b = sm + 145;
    const float* bf1w = sm + 209;    const float* bf1b = sm + 2257;
    const float* vf0w = sm + 2289;   const float* vf0b = sm + 3313;
    const float* vf1w = sm + 3345;   const float* vf1b = sm + 4401;
    const float* v20w = sm + 4434;   const float* v20b = sm + 5458;
    const float* v21w = sm + 5490;   const float* v21b = sm + 5522;
    const float* gf0wg = wp.p[16];   // GLOBAL
    const float* gf0b = sm + 5523;
    const float* gf1w = sm + 5555;   const float* gf1b = sm + 6067;
    const float* rd0w = sm + 6083;   const float* rd0b = sm + 6147;
    const float* rd1b = sm + 6163;   const float* b1s  = sm + 6195;

    float* T = sm + WTOT + wid * WARPTMP;
    float* tokW = T;          float* bottW = T + 128;  float* xW   = T + 384;
    float* gfW  = T + 640;    float* h256  = T + 768;  float* h33q = T + 1024;
    float* wtW  = T + 1168;   float* w0W   = T + 1176; float* mskW = T + 1184;
    float* visW = T + 1192;   float* w2W   = T + 1200;

    int t = blockIdx.x * 8 + wid;

    // dtype-robust invalid_features read
    const unsigned char* bb = (const unsigned char*)invG;
    int u8f = 0;
    for (int i = lane; i < 256; i += 32) if ((i & 3) && bb[i] == 1) u8f = 1;
    u8f = (__ballot_sync(0xffffffffu, u8f) != 0);

    for (int i = lane; i < 128; i += 32) tokW[i] = tokG[(size_t)t * 128 + i];
    float mv = 0.f;
    if (lane < 8) {
        int idx = t * 8 + lane;
        bool inv = u8f ? (bb[idx] != 0)
                       : (((const unsigned int*)invG)[idx] != 0u);
        mv = inv ? 0.f : 1.f;
    }
    float msum = wrsum(mv);
    if (lane < 8) { mskW[lane] = mv; wtW[lane] = mv / (msum + 1e-8f); }

    // ---- fused combine: bott = sum_p part + b1 + elu(rd-MLP), paired views
#pragma unroll
    for (int vp = 0; vp < 4; vp++) {
        size_t rA = (size_t)t * 8 + 2 * vp, rB = rA + 1;
        float rvA = (lane < 4) ? rdiff[rA * 4 + lane] : 0.f;
        float rvB = (lane < 4) ? rdiff[rB * 4 + lane] : 0.f;
        float a0 = __shfl_sync(0xffffffffu, rvA, 0), a1 = __shfl_sync(0xffffffffu, rvA, 1);
        float a2 = __shfl_sync(0xffffffffu, rvA, 2), a3 = __shfl_sync(0xffffffffu, rvA, 3);
        float c0 = __shfl_sync(0xffffffffu, rvB, 0), c1 = __shfl_sync(0xffffffffu, rvB, 1);
        float c2 = __shfl_sync(0xffffffffu, rvB, 2), c3 = __shfl_sync(0xffffffffu, rvB, 3);
        float h0 = 0.f, h1 = 0.f;
        if (lane < 16) {
            h0 = eluf(rd0b[lane] + a0 * rd0w[lane] + a1 * rd0w[16 + lane]
                                 + a2 * rd0w[32 + lane] + a3 * rd0w[48 + lane]);
            h1 = eluf(rd0b[lane] + c0 * rd0w[lane] + c1 * rd0w[16 + lane]
                                 + c2 * rd0w[32 + lane] + c3 * rd0w[48 + lane]);
        }
        float d0 = rd1b[lane], d1 = rd1b[lane];
#pragma unroll
        for (int k = 0; k < 16; k++) {
            float w = __ldg(&rd1w_[k * 32 + lane]);
            d0 += __shfl_sync(0xffffffffu, h0, k) * w;
            d1 += __shfl_sync(0xffffffffu, h1, k) * w;
        }
        float s0 = b1s[lane] + eluf(d0), s1 = b1s[lane] + eluf(d1);
#pragma unroll
        for (int p = 0; p < 4; p++) {
            s0 += g_part[(size_t)p * MROWS * 32 + rA * 32 + lane];
            s1 += g_part[(size_t)p * MROWS * 32 + rB * 32 + lane];
        }
        bottW[2 * vp * 32 + lane] = s0;
        bottW[(2 * vp + 1) * 32 + lane] = s1;
    }
    __syncwarp();

    // nr: 16 -> 8 (elu) -> 1, sigmoid, * weight
    if (lane < 8) {
        float hh[8];
#pragma unroll
        for (int i = 0; i < 8; i++) hh[i] = nr0b[i];
#pragma unroll
        for (int k = 0; k < 16; k++) {
            float tv = tokW[lane * 16 + k];
#pragma unroll
            for (int i = 0; i < 8; i++) hh[i] += tv * nr0w[k * 8 + i];
        }
        float s = nr1b[0];
#pragma unroll
        for (int i = 0; i < 8; i++) s += eluf(hh[i]) * nr1w[i];
        w0W[lane] = sigm(s) * wtW[lane];
    }
    __syncwarp();

    // weighted mean/var of bott
    {
        float m0 = 0.f, m1 = 0.f;
#pragma unroll
        for (int v = 0; v < 8; v++) { float b = bottW[v * 32 + lane]; m0 += b * w0W[v]; m1 += b * wtW[v]; }
        float v0 = 0.f, v1 = 0.f;
#pragma unroll
        for (int v = 0; v < 8; v++) {
            float b = bottW[v * 32 + lane]; float d0 = b - m0, d1 = b - m1;
            v0 += w0W[v] * d0 * d0; v1 += wtW[v] * d1 * d1;
        }
        gfW[lane] = m0; gfW[32 + lane] = v0; gfW[64 + lane] = m1; gfW[96 + lane] = v1;
    }
    __syncwarp();

    // hoisted globalfeat half of bf0 (float4 broadcasts of gfW)
    float gfc0 = bf0b[lane], gfc1 = bf0b[32 + lane];
#pragma unroll
    for (int k4 = 0; k4 < 32; k4++) {
        float4 g4 = *(float4*)&gfW[k4 * 4];
#pragma unroll
        for (int e = 0; e < 4; e++) {
            int k = k4 * 4 + e;
            float g = (&g4.x)[e];
            gfc0 += g * __ldg(&bf0wg[k * 64 + lane]);
            gfc1 += g * __ldg(&bf0wg[k * 64 + 32 + lane]);
        }
    }

    // ---- super-pair loop: 4 views per iteration, weights shared ----
#pragma unroll 1
    for (int sp = 0; sp < 2; sp++) {
        const int vb = sp * 4;
        // bf0 per-view part: 48 inputs -> 64 (elu)
        float a0[4], a1[4];
#pragma unroll
        for (int v = 0; v < 4; v++) { a0[v] = gfc0; a1[v] = gfc1; }
#pragma unroll
        for (int k4 = 0; k4 < 8; k4++) {
            float4 bv[4];
#pragma unroll
            for (int v = 0; v < 4; v++) bv[v] = *(float4*)&bottW[(vb + v) * 32 + k4 * 4];
#pragma unroll
            for (int e = 0; e < 4; e++) {
                int k = k4 * 4 + e;
                float w0 = __ldg(&bf0wg[(128 + k) * 64 + lane]);
                float w1 = __ldg(&bf0wg[(128 + k) * 64 + 32 + lane]);
#pragma unroll
                for (int v = 0; v < 4; v++) {
                    float f = (&bv[v].x)[e];
                    a0[v] += f * w0; a1[v] += f * w1;
                }
            }
        }
#pragma unroll
        for (int k4 = 0; k4 < 4; k4++) {
            float4 tv4[4];
#pragma unroll
            for (int v = 0; v < 4; v++) tv4[v] = *(float4*)&tokW[(vb + v) * 16 + k4 * 4];
#pragma unroll
            for (int e = 0; e < 4; e++) {
                int k = k4 * 4 + e;
                float w0 = __ldg(&bf0wg[(160 + k) * 64 + lane]);
                float w1 = __ldg(&bf0wg[(160 + k) * 64 + 32 + lane]);
#pragma unroll
                for (int v = 0; v < 4; v++) {
                    float f = (&tv4[v].x)[e];
                    a0[v] += f * w0; a1[v] += f * w1;
                }
            }
        }
#pragma unroll
        for (int v = 0; v < 4; v++) {
            h256[v * 64 + lane] = eluf(a0[v]);
            h256[v * 64 + 32 + lane] = eluf(a1[v]);
        }
        __syncwarp();
        // bf1: 64 -> 32 (elu)
        {
            float s[4];
#pragma unroll
            for (int v = 0; v < 4; v++) s[v] = bf1b[lane];
#pragma unroll
            for (int k4 = 0; k4 < 16; k4++) {
                float4 hv[4];
#pragma unroll
                for (int v = 0; v < 4; v++) hv[v] = *(float4*)&h256[v * 64 + k4 * 4];
#pragma unroll
                for (int e = 0; e < 4; e++) {
                    float w = bf1w[(k4 * 4 + e) * 32 + lane];
#pragma unroll
                    for (int v = 0; v < 4; v++) s[v] += (&hv[v].x)[e] * w;
                }
            }
#pragma unroll
            for (int v = 0; v < 4; v++) xW[(vb + v) * 32 + lane] = eluf(s[v]);
        }
        __syncwarp();
        // vf0 on x*weight (wv factored out)
        {
            float dot[4] = {0.f, 0.f, 0.f, 0.f};
#pragma unroll
            for (int k4 = 0; k4 < 8; k4++) {
                float4 xv[4];
#pragma unroll
                for (int v = 0; v < 4; v++) xv[v] = *(float4*)&xW[(vb + v) * 32 + k4 * 4];
#pragma unroll
                for (int e = 0; e < 4; e++) {
                    float w = vf0w[(k4 * 4 + e) * 32 + lane];
#pragma unroll
                    for (int v = 0; v < 4; v++) dot[v] += (&xv[v].x)[e] * w;
                }
            }
#pragma unroll
            for (int v = 0; v < 4; v++)
                h33q[v * 36 + lane] = eluf(vf0b[lane] + wtW[vb + v] * dot[v]);
        }
        __syncwarp();
        // vf1: 32 -> 33 (elu); col 32 handled by lanes 0..3 (one view each)
        float xr[4];
        {
#pragma unroll
            for (int v = 0; v < 4; v++) xr[v] = vf1b[lane];
#pragma unroll
            for (int k4 = 0; k4 < 8; k4++) {
                float4 hq[4];
#pragma unroll
                for (int v = 0; v < 4; v++) hq[v] = *(float4*)&h33q[v * 36 + k4 * 4];
#pragma unroll
                for (int e = 0; e < 4; e++) {
                    float w = vf1w[(k4 * 4 + e) * 33 + lane];
#pragma unroll
                    for (int v = 0; v < 4; v++) xr[v] += (&hq[v].x)[e] * w;
                }
            }
#pragma unroll
            for (int v = 0; v < 4; v++) xr[v] = eluf(xr[v]);
        }
        if (lane < 4) {
            const float* hx = &h33q[lane * 36];
            float a = vf1b[32];
#pragma unroll
            for (int k = 0; k < 32; k++) a += hx[k] * vf1w[k * 33 + 32];
            visW[vb + lane] = sigm(eluf(a)) * mskW[vb + lane];
        }
        __syncwarp();
#pragma unroll
        for (int v = 0; v < 4; v++) xW[(vb + v) * 32 + lane] += xr[v];
        __syncwarp();
        // v20 on x*vis (vv factored out)
        {
            float dot[4] = {0.f, 0.f, 0.f, 0.f};
#pragma unroll
            for (int k4 = 0; k4 < 8; k4++) {
                float4 xv[4];
#pragma unroll
                for (int v = 0; v < 4; v++) xv[v] = *(float4*)&xW[(vb + v) * 32 + k4 * 4];
#pragma unroll
                for (int e = 0; e < 4; e++) {
                    float w = v20w[(k4 * 4 + e) * 32 + lane];
#pragma unroll
                    for (int v = 0; v < 4; v++) dot[v] += (&xv[v].x)[e] * w;
                }
            }
#pragma unroll
            for (int v = 0; v < 4; v++)
                h33q[v * 36 + lane] = eluf(v20b[lane] + visW[vb + v] * dot[v]);
        }
        __syncwarp();
        {
            float wv21 = v21w[lane];
#pragma unroll
            for (int v = 0; v < 4; v++) {
                float s = wrsum(h33q[v * 36 + lane] * wv21) + v21b[0];
                if (lane == 0) w2W[vb + v] = sigm(s) * mskW[vb + v];
            }
        }
        __syncwarp();
    }

    // weight2 normalize + wbar
    {
        float vv = (lane < 8) ? w2W[lane] : 0.f;
        float s = wrsum(vv);
        if (lane < 8) w2W[lane] = vv / (s + 1e-8f);
    }
    __syncwarp();
    float wbar;
    {
        float vv = (lane < 8) ? w2W[lane] : 0.f;
        wbar = wrsum(vv) * 0.125f;
    }
    // weighted mean/var of x
    {
        float m = 0.f;
#pragma unroll
        for (int v = 0; v < 8; v++) m += xW[v * 32 + lane] * w2W[v];
        float va = 0.f;
#pragma unroll
        for (int v = 0; v < 8; v++) { float dd = xW[v * 32 + lane] - m; va += w2W[v] * dd * dd; }
        gfW[lane] = m; gfW[32 + lane] = va;
        if (lane == 0) gfW[64] = wbar;
    }
    __syncwarp();
    // gf: 65 -> 32 (elu) -> 16 (elu)   (gf0w from GLOBAL)
    {
        float a = gf0b[lane];
#pragma unroll
        for (int k4 = 0; k4 < 16; k4++) {
            float4 g4 = *(float4*)&gfW[k4 * 4];
#pragma unroll
            for (int e = 0; e < 4; e++)
                a += (&g4.x)[e] * __ldg(&gf0wg[(k4 * 4 + e) * 32 + lane]);
        }
        a += gfW[64] * __ldg(&gf0wg[64 * 32 + lane]);
        h33q[lane] = eluf(a);
    }
    __syncwarp();
    if (lane < 16) {
        float a = gf1b[lane];
#pragma unroll
        for (int k = 0; k < 32; k++) a += h33q[k] * gf1w[k * 16 + lane];
        out[(size_t)t * 16 + lane] = eluf(a);
    }
}

// ---------------------------------------------------------------------------
extern "C" void kernel_launch(void* const* d_in, const int* in_sizes, int n_in,
                              void* d_out, int out_size)
{
    const float* tok   = (const float*)d_in[0];
    const float* bott  = (const float*)d_in[1];
    const float* rdiff = (const float*)d_in[2];
    const void*  inval = (const void*)d_in[3];
    const float* rd0w = (const float*)d_in[4];  const float* rd0b = (const float*)d_in[5];
    const float* rd1w = (const float*)d_in[6];  const float* rd1b = (const float*)d_in[7];
    const float* if0w = (const float*)d_in[8];  const float* if0b = (const float*)d_in[9];
    const float* if1w = (const float*)d_in[10]; const float* if1b = (const float*)d_in[11];
    float* out = (float*)d_out;

    WPtrs wp;
    for (int i = 0; i < 20; i++) wp.p[i] = (const float*)d_in[12 + i];

    const int stage2_smem = (WTOT + 8 * WARPTMP) * 4;   // 63568 B -> 3 CTAs/SM
    cudaFuncSetAttribute(gemm1_kernel, cudaFuncAttributeMaxDynamicSharedMemorySize, SMEM_G1);
    cudaFuncSetAttribute(stage2_kernel, cudaFuncAttributeMaxDynamicSharedMemorySize, stage2_smem);

    prep_w0t<<<dim3(16, 64), dim3(32, 8)>>>(if0w);
    gemm1_kernel<<<dim3(4, 1024), 256, SMEM_G1>>>(bott, if0b, if1w);
    stage2_kernel<<<TOTPTS / 8, 256, stage2_smem>>>(tok, inval, rdiff, wp,
                                                    rd0w, rd0b, rd1w, rd1b, if1b, out);
}